// round 2
// baseline (speedup 1.0000x reference)
#include <cuda_runtime.h>
#include <cuda_bf16.h>
#include <cstdint>

// Problem constants
#define NNODES 50000
#define NEDGES 800000
#define IN_C   256
#define OUT_C  128

// Scratch: linear output y [N, OUT_C] and per-node edge counts.
// 16B-aligned: we issue float4 accesses against g_y.
__device__ __align__(16) float g_y[NNODES * OUT_C];
__device__ float g_counts[NNODES];

// ---------------------------------------------------------------------------
// Kernel 0: zero out + counts
// ---------------------------------------------------------------------------
__global__ void zero_kernel(float* __restrict__ out) {
    int total4 = (NNODES * OUT_C) / 4;   // 1.6M float4
    int i = blockIdx.x * blockDim.x + threadIdx.x;
    int stride = gridDim.x * blockDim.x;
    float4 z = make_float4(0.f, 0.f, 0.f, 0.f);
    for (int j = i; j < total4; j += stride)
        reinterpret_cast<float4*>(out)[j] = z;
    for (int j = i; j < NNODES; j += stride)
        g_counts[j] = 0.f;
}

// ---------------------------------------------------------------------------
// Kernel 1: GEMM  y[m, n] = sum_k x[m, k] * W[n, k] + b[n]
// BM=64, BN=128, BK=16; 256 threads (16x16); per-thread 4x8 register tile.
// ---------------------------------------------------------------------------
#define BM 64
#define BN 128
#define BK 16
#define TM 4
#define TN 8
#define AS_STRIDE (BM + 4)   // 68 floats
#define BS_STRIDE (BN + 4)   // 132 floats

__global__ __launch_bounds__(256) void gemm_kernel(
    const float* __restrict__ x,    // [N, 256]
    const float* __restrict__ W,    // [128, 256]
    const float* __restrict__ b)    // [128]
{
    __shared__ __align__(16) float As[BK * AS_STRIDE];  // [k][m]
    __shared__ __align__(16) float Bs[BK * BS_STRIDE];  // [k][n]

    const int tid = threadIdx.x;            // 0..255
    const int tx = tid & 15;                // 0..15  -> n tile
    const int ty = tid >> 4;                // 0..15  -> m tile
    const int block_m = blockIdx.x * BM;

    // Load mapping: each thread loads one float4 of A and two float4 of B per K-tile
    const int ld_row = tid >> 2;            // 0..63
    const int ld_k   = (tid & 3) * 4;       // 0,4,8,12

    float acc[TM][TN];
    #pragma unroll
    for (int i = 0; i < TM; i++)
        #pragma unroll
        for (int j = 0; j < TN; j++)
            acc[i][j] = 0.f;

    const int a_grow = block_m + ld_row;
    const bool a_ok = (a_grow < NNODES);

    for (int k0 = 0; k0 < IN_C; k0 += BK) {
        // --- Load A tile (64 rows x 16 k), transpose into As[k][m]
        float4 av = make_float4(0.f, 0.f, 0.f, 0.f);
        if (a_ok)
            av = *reinterpret_cast<const float4*>(x + (size_t)a_grow * IN_C + k0 + ld_k);
        As[(ld_k + 0) * AS_STRIDE + ld_row] = av.x;
        As[(ld_k + 1) * AS_STRIDE + ld_row] = av.y;
        As[(ld_k + 2) * AS_STRIDE + ld_row] = av.z;
        As[(ld_k + 3) * AS_STRIDE + ld_row] = av.w;

        // --- Load B tile (128 rows x 16 k), transpose into Bs[k][n]
        float4 bv0 = *reinterpret_cast<const float4*>(W + (size_t)ld_row * IN_C + k0 + ld_k);
        float4 bv1 = *reinterpret_cast<const float4*>(W + (size_t)(ld_row + 64) * IN_C + k0 + ld_k);
        Bs[(ld_k + 0) * BS_STRIDE + ld_row] = bv0.x;
        Bs[(ld_k + 1) * BS_STRIDE + ld_row] = bv0.y;
        Bs[(ld_k + 2) * BS_STRIDE + ld_row] = bv0.z;
        Bs[(ld_k + 3) * BS_STRIDE + ld_row] = bv0.w;
        Bs[(ld_k + 0) * BS_STRIDE + ld_row + 64] = bv1.x;
        Bs[(ld_k + 1) * BS_STRIDE + ld_row + 64] = bv1.y;
        Bs[(ld_k + 2) * BS_STRIDE + ld_row + 64] = bv1.z;
        Bs[(ld_k + 3) * BS_STRIDE + ld_row + 64] = bv1.w;

        __syncthreads();

        #pragma unroll
        for (int kk = 0; kk < BK; kk++) {
            float a[TM];
            float bb[TN];
            *reinterpret_cast<float4*>(a) =
                *reinterpret_cast<const float4*>(&As[kk * AS_STRIDE + ty * TM]);
            *reinterpret_cast<float4*>(bb) =
                *reinterpret_cast<const float4*>(&Bs[kk * BS_STRIDE + tx * TN]);
            *reinterpret_cast<float4*>(bb + 4) =
                *reinterpret_cast<const float4*>(&Bs[kk * BS_STRIDE + tx * TN + 4]);
            #pragma unroll
            for (int i = 0; i < TM; i++)
                #pragma unroll
                for (int j = 0; j < TN; j++)
                    acc[i][j] = fmaf(a[i], bb[j], acc[i][j]);
        }
        __syncthreads();
    }

    // Epilogue: add bias, store
    #pragma unroll
    for (int i = 0; i < TM; i++) {
        int m = block_m + ty * TM + i;
        if (m >= NNODES) break;
        #pragma unroll
        for (int j = 0; j < TN; j += 4) {
            int n = tx * TN + j;
            float4 v;
            v.x = acc[i][j + 0] + b[n + 0];
            v.y = acc[i][j + 1] + b[n + 1];
            v.z = acc[i][j + 2] + b[n + 2];
            v.w = acc[i][j + 3] + b[n + 3];
            *reinterpret_cast<float4*>(&g_y[(size_t)m * OUT_C + n]) = v;
        }
    }
}

// ---------------------------------------------------------------------------
// Kernel 2: scatter-add. One warp per edge; lane l handles cols [4l, 4l+4).
// edge_index is int32 (JAX demotes int64 under default x64-disabled config).
// ---------------------------------------------------------------------------
__global__ __launch_bounds__(256) void scatter_kernel(
    const int* __restrict__ ei,   // [2, E]: src row then dst row
    float* __restrict__ out)
{
    int gwarp = (blockIdx.x * blockDim.x + threadIdx.x) >> 5;
    int lane = threadIdx.x & 31;
    if (gwarp >= NEDGES) return;

    int src = ei[gwarp];
    int dst = ei[NEDGES + gwarp];

    const float4 v = *reinterpret_cast<const float4*>(&g_y[(size_t)src * OUT_C + lane * 4]);
    float* o = out + (size_t)dst * OUT_C + lane * 4;
    asm volatile("red.global.add.v4.f32 [%0], {%1, %2, %3, %4};"
                 :: "l"(o), "f"(v.x), "f"(v.y), "f"(v.z), "f"(v.w)
                 : "memory");
    if (lane == 0)
        atomicAdd(&g_counts[dst], 1.0f);
}

// ---------------------------------------------------------------------------
// Kernel 3: finalize — divide each row by max(count, 1)
// ---------------------------------------------------------------------------
__global__ __launch_bounds__(256) void finalize_kernel(float* __restrict__ out) {
    int total4 = NNODES * (OUT_C / 4);   // one float4 per thread
    int i = blockIdx.x * blockDim.x + threadIdx.x;
    if (i >= total4) return;
    int n = i >> 5;                      // node index (32 float4 per row)
    float c = g_counts[n];
    float inv = 1.0f / fmaxf(c, 1.0f);
    float4 v = reinterpret_cast<float4*>(out)[i];
    v.x *= inv; v.y *= inv; v.z *= inv; v.w *= inv;
    reinterpret_cast<float4*>(out)[i] = v;
}

// ---------------------------------------------------------------------------
extern "C" void kernel_launch(void* const* d_in, const int* in_sizes, int n_in,
                              void* d_out, int out_size) {
    const float* x  = (const float*)d_in[0];
    const int*   ei = (const int*)d_in[1];
    const float* W  = (const float*)d_in[2];
    const float* b  = (const float*)d_in[3];
    float* out = (float*)d_out;

    // 0: zero output + counts
    zero_kernel<<<1024, 256>>>(out);

    // 1: GEMM y = x W^T + b
    gemm_kernel<<<(NNODES + BM - 1) / BM, 256>>>(x, W, b);

    // 2: scatter-add (warp per edge)
    int warps_per_block = 256 / 32;
    int blocks = (NEDGES + warps_per_block - 1) / warps_per_block;
    scatter_kernel<<<blocks, 256>>>(ei, out);

    // 3: finalize (mean)
    int total4 = NNODES * (OUT_C / 4);
    finalize_kernel<<<(total4 + 255) / 256, 256>>>(out);
}

// round 3
// speedup vs baseline: 1.5342x; 1.5342x over previous
#include <cuda_runtime.h>
#include <cuda_bf16.h>
#include <cstdint>

// Problem constants
#define NNODES 50000
#define NEDGES 800000
#define IN_C   256
#define OUT_C  128

// Scratch: linear output y [N, OUT_C] and per-node edge counts.
__device__ __align__(16) float g_y[NNODES * OUT_C];
__device__ float g_counts[NNODES];

// ---------------------------------------------------------------------------
// Kernel 0: zero out + counts
// ---------------------------------------------------------------------------
__global__ void zero_kernel(float* __restrict__ out) {
    int total4 = (NNODES * OUT_C) / 4;
    int i = blockIdx.x * blockDim.x + threadIdx.x;
    int stride = gridDim.x * blockDim.x;
    float4 z = make_float4(0.f, 0.f, 0.f, 0.f);
    for (int j = i; j < total4; j += stride)
        reinterpret_cast<float4*>(out)[j] = z;
    for (int j = i; j < NNODES; j += stride)
        g_counts[j] = 0.f;
}

// ---------------------------------------------------------------------------
// Kernel 1: tf32 tensor-core GEMM  y[m,n] = sum_k x[m,k] * W[n,k] + b[n]
// BM=128, BN=128 (= OUT_C), BK=16. 256 threads = 8 warps in 4x2 (m x n).
// Warp tile 32x64 = 2 x 8 fragments of mma.m16n8k8.tf32.
// Smem stride 136 (mod 32 = 8) -> conflict-free fragment LDS.
// ---------------------------------------------------------------------------
#define GBM 128
#define GBK 16
#define SSTRIDE 136   // floats per k-row in smem

__device__ __forceinline__ uint32_t f32_to_tf32(float f) {
    uint32_t r;
    asm("cvt.rna.tf32.f32 %0, %1;" : "=r"(r) : "f"(f));
    return r;
}

__global__ __launch_bounds__(256) void gemm_tf32_kernel(
    const float* __restrict__ x,    // [N, 256]
    const float* __restrict__ W,    // [128, 256]
    const float* __restrict__ b)    // [128]
{
    __shared__ uint32_t As[GBK * SSTRIDE];  // [k][m], tf32 bits
    __shared__ uint32_t Bs[GBK * SSTRIDE];  // [k][n], tf32 bits

    const int tid  = threadIdx.x;
    const int lane = tid & 31;
    const int warp = tid >> 5;          // 0..7
    const int wm   = warp >> 1;         // 0..3 -> m offset wm*32
    const int wn   = warp & 1;          // 0..1 -> n offset wn*64
    const int block_m = blockIdx.x * GBM;

    const int grp = lane >> 2;          // groupID 0..7
    const int qid = lane & 3;           // thread-in-group 0..3

    float acc[2][8][4];
    #pragma unroll
    for (int i = 0; i < 2; i++)
        #pragma unroll
        for (int j = 0; j < 8; j++)
            #pragma unroll
            for (int c = 0; c < 4; c++)
                acc[i][j][c] = 0.f;

    for (int k0 = 0; k0 < IN_C; k0 += GBK) {
        // ---- Load tiles: each thread handles 2 float4 of A and 2 of B.
        #pragma unroll
        for (int u = 0; u < 2; u++) {
            int idx = tid * 2 + u;          // 0..511
            int row = idx >> 2;             // 0..127
            int kq  = (idx & 3) * 4;        // 0,4,8,12

            // A: x[block_m + row][k0 + kq .. +3]
            float4 av = make_float4(0.f, 0.f, 0.f, 0.f);
            int gm = block_m + row;
            if (gm < NNODES)
                av = *reinterpret_cast<const float4*>(x + (size_t)gm * IN_C + k0 + kq);
            As[(kq + 0) * SSTRIDE + row] = f32_to_tf32(av.x);
            As[(kq + 1) * SSTRIDE + row] = f32_to_tf32(av.y);
            As[(kq + 2) * SSTRIDE + row] = f32_to_tf32(av.z);
            As[(kq + 3) * SSTRIDE + row] = f32_to_tf32(av.w);

            // B: W[row][k0 + kq .. +3]   (row = output channel n)
            float4 bv = *reinterpret_cast<const float4*>(W + (size_t)row * IN_C + k0 + kq);
            Bs[(kq + 0) * SSTRIDE + row] = f32_to_tf32(bv.x);
            Bs[(kq + 1) * SSTRIDE + row] = f32_to_tf32(bv.y);
            Bs[(kq + 2) * SSTRIDE + row] = f32_to_tf32(bv.z);
            Bs[(kq + 3) * SSTRIDE + row] = f32_to_tf32(bv.w);
        }
        __syncthreads();

        // ---- Two k8 steps per tile
        #pragma unroll
        for (int s = 0; s < 2; s++) {
            const int kk = s * 8 + qid;     // k row for a0/b0; +4 for a2/b1

            uint32_t af[2][4];
            #pragma unroll
            for (int i = 0; i < 2; i++) {
                int rm = wm * 32 + i * 16 + grp;
                af[i][0] = As[kk * SSTRIDE + rm];
                af[i][1] = As[kk * SSTRIDE + rm + 8];
                af[i][2] = As[(kk + 4) * SSTRIDE + rm];
                af[i][3] = As[(kk + 4) * SSTRIDE + rm + 8];
            }
            uint32_t bf[8][2];
            #pragma unroll
            for (int j = 0; j < 8; j++) {
                int bn = wn * 64 + j * 8 + grp;
                bf[j][0] = Bs[kk * SSTRIDE + bn];
                bf[j][1] = Bs[(kk + 4) * SSTRIDE + bn];
            }
            #pragma unroll
            for (int i = 0; i < 2; i++)
                #pragma unroll
                for (int j = 0; j < 8; j++) {
                    asm volatile(
                        "mma.sync.aligned.m16n8k8.row.col.f32.tf32.tf32.f32 "
                        "{%0,%1,%2,%3}, {%4,%5,%6,%7}, {%8,%9}, {%0,%1,%2,%3};\n"
                        : "+f"(acc[i][j][0]), "+f"(acc[i][j][1]),
                          "+f"(acc[i][j][2]), "+f"(acc[i][j][3])
                        : "r"(af[i][0]), "r"(af[i][1]), "r"(af[i][2]), "r"(af[i][3]),
                          "r"(bf[j][0]), "r"(bf[j][1]));
                }
        }
        __syncthreads();
    }

    // ---- Epilogue: bias + store (float2 per c-pair)
    #pragma unroll
    for (int i = 0; i < 2; i++) {
        int r0 = block_m + wm * 32 + i * 16 + grp;
        int r1 = r0 + 8;
        #pragma unroll
        for (int j = 0; j < 8; j++) {
            int col = wn * 64 + j * 8 + qid * 2;
            float b0 = b[col], b1 = b[col + 1];
            if (r0 < NNODES) {
                float2 v = make_float2(acc[i][j][0] + b0, acc[i][j][1] + b1);
                *reinterpret_cast<float2*>(&g_y[(size_t)r0 * OUT_C + col]) = v;
            }
            if (r1 < NNODES) {
                float2 v = make_float2(acc[i][j][2] + b0, acc[i][j][3] + b1);
                *reinterpret_cast<float2*>(&g_y[(size_t)r1 * OUT_C + col]) = v;
            }
        }
    }
}

// ---------------------------------------------------------------------------
// Kernel 2: scatter-add. One warp per edge; lane l handles cols [4l, 4l+4).
// edge_index is int32.
// ---------------------------------------------------------------------------
__global__ __launch_bounds__(256) void scatter_kernel(
    const int* __restrict__ ei,   // [2, E]: src row then dst row
    float* __restrict__ out)
{
    int gwarp = (blockIdx.x * blockDim.x + threadIdx.x) >> 5;
    int lane = threadIdx.x & 31;
    if (gwarp >= NEDGES) return;

    int src = ei[gwarp];
    int dst = ei[NEDGES + gwarp];

    const float4 v = *reinterpret_cast<const float4*>(&g_y[(size_t)src * OUT_C + lane * 4]);
    float* o = out + (size_t)dst * OUT_C + lane * 4;
    asm volatile("red.global.add.v4.f32 [%0], {%1, %2, %3, %4};"
                 :: "l"(o), "f"(v.x), "f"(v.y), "f"(v.z), "f"(v.w)
                 : "memory");
    if (lane == 0)
        atomicAdd(&g_counts[dst], 1.0f);
}

// ---------------------------------------------------------------------------
// Kernel 3: finalize — divide each row by max(count, 1)
// ---------------------------------------------------------------------------
__global__ __launch_bounds__(256) void finalize_kernel(float* __restrict__ out) {
    int total4 = NNODES * (OUT_C / 4);
    int i = blockIdx.x * blockDim.x + threadIdx.x;
    if (i >= total4) return;
    int n = i >> 5;
    float c = g_counts[n];
    float inv = 1.0f / fmaxf(c, 1.0f);
    float4 v = reinterpret_cast<float4*>(out)[i];
    v.x *= inv; v.y *= inv; v.z *= inv; v.w *= inv;
    reinterpret_cast<float4*>(out)[i] = v;
}

// ---------------------------------------------------------------------------
extern "C" void kernel_launch(void* const* d_in, const int* in_sizes, int n_in,
                              void* d_out, int out_size) {
    const float* x  = (const float*)d_in[0];
    const int*   ei = (const int*)d_in[1];
    const float* W  = (const float*)d_in[2];
    const float* b  = (const float*)d_in[3];
    float* out = (float*)d_out;

    zero_kernel<<<1024, 256>>>(out);

    gemm_tf32_kernel<<<(NNODES + GBM - 1) / GBM, 256>>>(x, W, b);

    int warps_per_block = 256 / 32;
    int blocks = (NEDGES + warps_per_block - 1) / warps_per_block;
    scatter_kernel<<<blocks, 256>>>(ei, out);

    int total4 = NNODES * (OUT_C / 4);
    finalize_kernel<<<(total4 + 255) / 256, 256>>>(out);
}